// round 1
// baseline (speedup 1.0000x reference)
#include <cuda_runtime.h>
#include <cuda_bf16.h>
#include <math.h>

#define Cc 512
#define Bb 8
#define Nn 4096            // H*W
#define GROUPS 8
#define EPS 1e-5f

// ---------------- scratch (device globals; no allocs allowed) ----------------
__device__ float g_h[(size_t)Bb * Nn * Cc];   // groupnormed tokens, later attn-out
__device__ float g_q[(size_t)Bb * Nn * Cc];   // q, later final proj out (y)
__device__ float g_k[(size_t)Bb * Nn * Cc];
__device__ float g_v[(size_t)Bb * Nn * Cc];
__device__ float g_s[(size_t)Bb * Nn * Nn];   // scores / probs (512 MB)
__device__ float g_stats[Bb * GROUPS * 2];    // mu, rstd

// ---------------- 1) group-norm statistics ----------------
// One block per (b, g). Each group's data is a contiguous 64*4096 float chunk.
__global__ void gn_stats_kernel(const float* __restrict__ x) {
    int bg = blockIdx.x;                 // 0..63
    const size_t cnt = (size_t)(Cc / GROUPS) * Nn;     // 262144
    const float4* p = (const float4*)(x + (size_t)bg * cnt);
    int tid = threadIdx.x;
    float s = 0.f, sq = 0.f;
    for (int i = tid; i < (int)(cnt / 4); i += blockDim.x) {
        float4 v = p[i];
        s  += v.x + v.y + v.z + v.w;
        sq += v.x * v.x + v.y * v.y + v.z * v.z + v.w * v.w;
    }
    __shared__ float ss[256], ssq[256];
    ss[tid] = s; ssq[tid] = sq;
    __syncthreads();
    for (int o = 128; o > 0; o >>= 1) {
        if (tid < o) { ss[tid] += ss[tid + o]; ssq[tid] += ssq[tid + o]; }
        __syncthreads();
    }
    if (tid == 0) {
        float mu  = ss[0] / (float)cnt;
        float var = ssq[0] / (float)cnt - mu * mu;
        g_stats[bg * 2 + 0] = mu;
        g_stats[bg * 2 + 1] = rsqrtf(var + EPS);
    }
}

// ---------------- 2) apply GN + transpose [B,C,N] -> [B,N,C] ----------------
__global__ void gn_apply_kernel(const float* __restrict__ x,
                                const float* __restrict__ w,
                                const float* __restrict__ b) {
    __shared__ float sm[32][33];
    int bz = blockIdx.z;
    int n0 = blockIdx.x * 32;
    int c0 = blockIdx.y * 32;
    int tx = threadIdx.x, ty = threadIdx.y;
    {
        int c = c0 + ty, n = n0 + tx;
        int g = c >> 6;
        float mu   = g_stats[(bz * GROUPS + g) * 2 + 0];
        float rstd = g_stats[(bz * GROUPS + g) * 2 + 1];
        float v = x[((size_t)bz * Cc + c) * Nn + n];
        sm[ty][tx] = (v - mu) * rstd * w[c] + b[c];
    }
    __syncthreads();
    {
        int n = n0 + ty, c = c0 + tx;
        g_h[((size_t)bz * Nn + n) * Cc + c] = sm[tx][ty];
    }
}

// ---------------- SGEMM C = alpha * A·B^T (+bias), both K-major ----------------
// BM=BN=128, BK=8, 256 threads, 8x8 per thread. All dims divisible.
#define BM 128
#define BN 128
#define BK 8
#define PAD 4

__global__ __launch_bounds__(256, 2)
void sgemm_tn(const float* __restrict__ A, const float* __restrict__ B,
              const float* __restrict__ bias, float* __restrict__ C,
              int M, int N, int K, float alpha,
              long long sA, long long sB, long long sC) {
    A += (long long)blockIdx.z * sA;
    B += (long long)blockIdx.z * sB;
    C += (long long)blockIdx.z * sC;
    __shared__ float As[BK][BM + PAD];
    __shared__ float Bs[BK][BN + PAD];
    int tid = threadIdx.x;
    int brow = blockIdx.y * BM;
    int bcol = blockIdx.x * BN;
    int lr = tid >> 1;             // 0..127
    int lk = (tid & 1) * 4;        // 0 or 4
    int tr = (tid >> 4) * 8;       // 0..120
    int tc = (tid & 15) * 8;
    float acc[8][8];
    #pragma unroll
    for (int i = 0; i < 8; i++)
        #pragma unroll
        for (int j = 0; j < 8; j++) acc[i][j] = 0.f;

    const float* Ap = A + (long long)(brow + lr) * K + lk;
    const float* Bp = B + (long long)(bcol + lr) * K + lk;
    for (int k0 = 0; k0 < K; k0 += BK) {
        float4 av = *(const float4*)(Ap + k0);
        float4 bv = *(const float4*)(Bp + k0);
        As[lk + 0][lr] = av.x; As[lk + 1][lr] = av.y;
        As[lk + 2][lr] = av.z; As[lk + 3][lr] = av.w;
        Bs[lk + 0][lr] = bv.x; Bs[lk + 1][lr] = bv.y;
        Bs[lk + 2][lr] = bv.z; Bs[lk + 3][lr] = bv.w;
        __syncthreads();
        #pragma unroll
        for (int k = 0; k < BK; k++) {
            float4 a0 = *(const float4*)&As[k][tr];
            float4 a1 = *(const float4*)&As[k][tr + 4];
            float4 b0 = *(const float4*)&Bs[k][tc];
            float4 b1 = *(const float4*)&Bs[k][tc + 4];
            float ar[8] = {a0.x, a0.y, a0.z, a0.w, a1.x, a1.y, a1.z, a1.w};
            float br[8] = {b0.x, b0.y, b0.z, b0.w, b1.x, b1.y, b1.z, b1.w};
            #pragma unroll
            for (int i = 0; i < 8; i++)
                #pragma unroll
                for (int j = 0; j < 8; j++)
                    acc[i][j] = fmaf(ar[i], br[j], acc[i][j]);
        }
        __syncthreads();
    }
    #pragma unroll
    for (int i = 0; i < 8; i++) {
        long long row = brow + tr + i;
        #pragma unroll
        for (int j = 0; j < 8; j += 4) {
            int col = bcol + tc + j;
            float4 o;
            o.x = acc[i][j + 0] * alpha;
            o.y = acc[i][j + 1] * alpha;
            o.z = acc[i][j + 2] * alpha;
            o.w = acc[i][j + 3] * alpha;
            if (bias) {
                o.x += bias[col + 0]; o.y += bias[col + 1];
                o.z += bias[col + 2]; o.w += bias[col + 3];
            }
            *(float4*)(C + row * N + col) = o;
        }
    }
}

// ---------------- SGEMM C = A·B  (A K-major, B [K,N] N-major) ----------------
__global__ __launch_bounds__(256, 2)
void sgemm_nn(const float* __restrict__ A, const float* __restrict__ B,
              float* __restrict__ C,
              int M, int N, int K,
              long long sA, long long sB, long long sC) {
    A += (long long)blockIdx.z * sA;
    B += (long long)blockIdx.z * sB;
    C += (long long)blockIdx.z * sC;
    __shared__ float As[BK][BM + PAD];
    __shared__ float Bs[BK][BN + PAD];
    int tid = threadIdx.x;
    int brow = blockIdx.y * BM;
    int bcol = blockIdx.x * BN;
    int lr = tid >> 1;
    int lk = (tid & 1) * 4;
    int kr = tid >> 5;             // 0..7
    int nc = (tid & 31) * 4;       // 0..124
    int tr = (tid >> 4) * 8;
    int tc = (tid & 15) * 8;
    float acc[8][8];
    #pragma unroll
    for (int i = 0; i < 8; i++)
        #pragma unroll
        for (int j = 0; j < 8; j++) acc[i][j] = 0.f;

    const float* Ap = A + (long long)(brow + lr) * K + lk;
    const float* Bp = B + (long long)kr * N + bcol + nc;
    for (int k0 = 0; k0 < K; k0 += BK) {
        float4 av = *(const float4*)(Ap + k0);
        float4 bv = *(const float4*)(Bp + (long long)k0 * N);
        As[lk + 0][lr] = av.x; As[lk + 1][lr] = av.y;
        As[lk + 2][lr] = av.z; As[lk + 3][lr] = av.w;
        *(float4*)&Bs[kr][nc] = bv;
        __syncthreads();
        #pragma unroll
        for (int k = 0; k < BK; k++) {
            float4 a0 = *(const float4*)&As[k][tr];
            float4 a1 = *(const float4*)&As[k][tr + 4];
            float4 b0 = *(const float4*)&Bs[k][tc];
            float4 b1 = *(const float4*)&Bs[k][tc + 4];
            float ar[8] = {a0.x, a0.y, a0.z, a0.w, a1.x, a1.y, a1.z, a1.w};
            float br[8] = {b0.x, b0.y, b0.z, b0.w, b1.x, b1.y, b1.z, b1.w};
            #pragma unroll
            for (int i = 0; i < 8; i++)
                #pragma unroll
                for (int j = 0; j < 8; j++)
                    acc[i][j] = fmaf(ar[i], br[j], acc[i][j]);
        }
        __syncthreads();
    }
    #pragma unroll
    for (int i = 0; i < 8; i++) {
        long long row = brow + tr + i;
        #pragma unroll
        for (int j = 0; j < 8; j += 4) {
            int col = bcol + tc + j;
            float4 o = {acc[i][j], acc[i][j + 1], acc[i][j + 2], acc[i][j + 3]};
            *(float4*)(C + row * N + col) = o;
        }
    }
}

// ---------------- softmax over rows of g_s (row length 4096) ----------------
__global__ void softmax_kernel() {
    size_t row = blockIdx.x;
    float4* p = (float4*)(g_s + row * Nn);
    int tid = threadIdx.x;
    float4 v[4];
    float mx = -1e30f;
    #pragma unroll
    for (int i = 0; i < 4; i++) {
        v[i] = p[tid + i * 256];
        mx = fmaxf(mx, fmaxf(fmaxf(v[i].x, v[i].y), fmaxf(v[i].z, v[i].w)));
    }
    __shared__ float sm[256];
    sm[tid] = mx; __syncthreads();
    for (int o = 128; o > 0; o >>= 1) {
        if (tid < o) sm[tid] = fmaxf(sm[tid], sm[tid + o]);
        __syncthreads();
    }
    mx = sm[0];
    __syncthreads();
    float s = 0.f;
    #pragma unroll
    for (int i = 0; i < 4; i++) {
        v[i].x = __expf(v[i].x - mx); v[i].y = __expf(v[i].y - mx);
        v[i].z = __expf(v[i].z - mx); v[i].w = __expf(v[i].w - mx);
        s += v[i].x + v[i].y + v[i].z + v[i].w;
    }
    sm[tid] = s; __syncthreads();
    for (int o = 128; o > 0; o >>= 1) {
        if (tid < o) sm[tid] += sm[tid + o];
        __syncthreads();
    }
    float inv = 1.f / sm[0];
    #pragma unroll
    for (int i = 0; i < 4; i++) {
        v[i].x *= inv; v[i].y *= inv; v[i].z *= inv; v[i].w *= inv;
        p[tid + i * 256] = v[i];
    }
}

// ---------------- residual: out[b,c,n] = x[b,c,n] + y[b,n,c] ----------------
__global__ void residual_kernel(const float* __restrict__ x, float* __restrict__ out) {
    __shared__ float sm[32][33];
    int bz = blockIdx.z;
    int n0 = blockIdx.x * 32;
    int c0 = blockIdx.y * 32;
    int tx = threadIdx.x, ty = threadIdx.y;
    // read y (in g_q) coalesced along c
    sm[ty][tx] = g_q[((size_t)bz * Nn + (n0 + ty)) * Cc + (c0 + tx)];
    __syncthreads();
    size_t idx = ((size_t)bz * Cc + (c0 + ty)) * Nn + (n0 + tx);
    out[idx] = x[idx] + sm[tx][ty];
}

// ---------------- launch ----------------
extern "C" void kernel_launch(void* const* d_in, const int* in_sizes, int n_in,
                              void* d_out, int out_size) {
    const float* x    = (const float*)d_in[0];
    const float* gn_w = (const float*)d_in[1];
    const float* gn_b = (const float*)d_in[2];
    const float* wq   = (const float*)d_in[3];
    const float* bq   = (const float*)d_in[4];
    const float* wk   = (const float*)d_in[5];
    const float* bk   = (const float*)d_in[6];
    const float* wv   = (const float*)d_in[7];
    const float* bv   = (const float*)d_in[8];
    const float* wo   = (const float*)d_in[9];
    const float* bo   = (const float*)d_in[10];
    float* out = (float*)d_out;

    float *h, *q, *k, *v, *s;
    cudaGetSymbolAddress((void**)&h, g_h);
    cudaGetSymbolAddress((void**)&q, g_q);
    cudaGetSymbolAddress((void**)&k, g_k);
    cudaGetSymbolAddress((void**)&v, g_v);
    cudaGetSymbolAddress((void**)&s, g_s);

    const long long NC = (long long)Nn * Cc;           // 2M
    const long long NN = (long long)Nn * Nn;           // 16M
    const int Mtot = Bb * Nn;                          // 32768
    const float scale = 0.044194173824159216f;         // 1/sqrt(512)

    // 1) GN stats
    gn_stats_kernel<<<Bb * GROUPS, 256>>>(x);
    // 2) GN apply + transpose
    gn_apply_kernel<<<dim3(Nn / 32, Cc / 32, Bb), dim3(32, 32)>>>(x, gn_w, gn_b);
    // 3) Q, K, V projections (single big GEMM each: [32768,512] x [512,512]^T)
    dim3 gproj(Cc / BN, Mtot / BM, 1);
    sgemm_tn<<<gproj, 256>>>(h, wq, bq, q, Mtot, Cc, Cc, 1.f, 0, 0, 0);
    sgemm_tn<<<gproj, 256>>>(h, wk, bk, k, Mtot, Cc, Cc, 1.f, 0, 0, 0);
    sgemm_tn<<<gproj, 256>>>(h, wv, bv, v, Mtot, Cc, Cc, 1.f, 0, 0, 0);
    // 4) scores = q k^T * scale  (batched)
    sgemm_tn<<<dim3(Nn / BN, Nn / BM, Bb), 256>>>(q, k, nullptr, s,
                                                  Nn, Nn, Cc, scale, NC, NC, NN);
    // 5) softmax rows
    softmax_kernel<<<Bb * Nn, 256>>>();
    // 6) attn @ V  -> reuse g_h
    sgemm_nn<<<dim3(Cc / BN, Nn / BM, Bb), 256>>>(s, v, h, Nn, Cc, Nn, NN, NC, NC);
    // 7) output projection -> reuse g_q
    sgemm_tn<<<gproj, 256>>>(h, wo, bo, q, Mtot, Cc, Cc, 1.f, 0, 0, 0);
    // 8) residual + transpose back
    residual_kernel<<<dim3(Nn / 32, Cc / 32, Bb), dim3(32, 32)>>>(x, out);
}

// round 2
// speedup vs baseline: 1.0533x; 1.0533x over previous
#include <cuda_runtime.h>
#include <cuda_bf16.h>
#include <math.h>

#define Cc 512
#define Bb 8
#define Nn 4096            // H*W
#define GROUPS 8
#define EPS 1e-5f

// ---------------- scratch (device globals; no allocs allowed) ----------------
__device__ float g_h[(size_t)Bb * Nn * Cc];   // groupnormed tokens, later attn-out
__device__ float g_q[(size_t)Bb * Nn * Cc];   // q, later final proj out (y)
__device__ float g_k[(size_t)Bb * Nn * Cc];
__device__ float g_v[(size_t)Bb * Nn * Cc];
__device__ float g_s[(size_t)Bb * Nn * Nn];   // scores / probs (512 MB)
__device__ float g_stats[Bb * GROUPS * 2];    // mu, rstd

// ---------------- 1) group-norm statistics ----------------
// One block per (b, g). Each group's data is a contiguous 64*4096 float chunk.
__global__ void gn_stats_kernel(const float* __restrict__ x) {
    int bg = blockIdx.x;                 // 0..63
    const size_t cnt = (size_t)(Cc / GROUPS) * Nn;     // 262144
    const float4* p = (const float4*)(x + (size_t)bg * cnt);
    int tid = threadIdx.x;
    float s = 0.f, sq = 0.f;
    for (int i = tid; i < (int)(cnt / 4); i += blockDim.x) {
        float4 v = p[i];
        s  += v.x + v.y + v.z + v.w;
        sq += v.x * v.x + v.y * v.y + v.z * v.z + v.w * v.w;
    }
    __shared__ float ss[256], ssq[256];
    ss[tid] = s; ssq[tid] = sq;
    __syncthreads();
    for (int o = 128; o > 0; o >>= 1) {
        if (tid < o) { ss[tid] += ss[tid + o]; ssq[tid] += ssq[tid + o]; }
        __syncthreads();
    }
    if (tid == 0) {
        float mu  = ss[0] / (float)cnt;
        float var = ssq[0] / (float)cnt - mu * mu;
        g_stats[bg * 2 + 0] = mu;
        g_stats[bg * 2 + 1] = rsqrtf(var + EPS);
    }
}

// ---------------- 2) apply GN + transpose [B,C,N] -> [B,N,C] ----------------
__global__ void gn_apply_kernel(const float* __restrict__ x,
                                const float* __restrict__ w,
                                const float* __restrict__ b) {
    __shared__ float sm[32][33];
    int bz = blockIdx.z;
    int n0 = blockIdx.x * 32;
    int c0 = blockIdx.y * 32;
    int tx = threadIdx.x, ty = threadIdx.y;
    {
        int c = c0 + ty, n = n0 + tx;
        int g = c >> 6;
        float mu   = g_stats[(bz * GROUPS + g) * 2 + 0];
        float rstd = g_stats[(bz * GROUPS + g) * 2 + 1];
        float v = x[((size_t)bz * Cc + c) * Nn + n];
        sm[ty][tx] = (v - mu) * rstd * w[c] + b[c];
    }
    __syncthreads();
    {
        int n = n0 + ty, c = c0 + tx;
        g_h[((size_t)bz * Nn + n) * Cc + c] = sm[tx][ty];
    }
}

// ---------------- SGEMM C = alpha * A·B^T (+bias), both K-major ----------------
// BM=BN=128, BK=8, 256 threads, 8x8 per thread. All dims divisible.
#define BM 128
#define BN 128
#define BK 8
#define PAD 4

__global__ __launch_bounds__(256, 2)
void sgemm_tn(const float* __restrict__ A, const float* __restrict__ B,
              const float* __restrict__ bias, float* __restrict__ C,
              int M, int N, int K, float alpha,
              long long sA, long long sB, long long sC) {
    A += (long long)blockIdx.z * sA;
    B += (long long)blockIdx.z * sB;
    C += (long long)blockIdx.z * sC;
    __shared__ float As[BK][BM + PAD];
    __shared__ float Bs[BK][BN + PAD];
    int tid = threadIdx.x;
    int brow = blockIdx.y * BM;
    int bcol = blockIdx.x * BN;
    int lr = tid >> 1;             // 0..127
    int lk = (tid & 1) * 4;        // 0 or 4
    int tr = (tid >> 4) * 8;       // 0..120
    int tc = (tid & 15) * 8;
    float acc[8][8];
    #pragma unroll
    for (int i = 0; i < 8; i++)
        #pragma unroll
        for (int j = 0; j < 8; j++) acc[i][j] = 0.f;

    const float* Ap = A + (long long)(brow + lr) * K + lk;
    const float* Bp = B + (long long)(bcol + lr) * K + lk;
    for (int k0 = 0; k0 < K; k0 += BK) {
        float4 av = *(const float4*)(Ap + k0);
        float4 bv = *(const float4*)(Bp + k0);
        As[lk + 0][lr] = av.x; As[lk + 1][lr] = av.y;
        As[lk + 2][lr] = av.z; As[lk + 3][lr] = av.w;
        Bs[lk + 0][lr] = bv.x; Bs[lk + 1][lr] = bv.y;
        Bs[lk + 2][lr] = bv.z; Bs[lk + 3][lr] = bv.w;
        __syncthreads();
        #pragma unroll
        for (int k = 0; k < BK; k++) {
            float4 a0 = *(const float4*)&As[k][tr];
            float4 a1 = *(const float4*)&As[k][tr + 4];
            float4 b0 = *(const float4*)&Bs[k][tc];
            float4 b1 = *(const float4*)&Bs[k][tc + 4];
            float ar[8] = {a0.x, a0.y, a0.z, a0.w, a1.x, a1.y, a1.z, a1.w};
            float br[8] = {b0.x, b0.y, b0.z, b0.w, b1.x, b1.y, b1.z, b1.w};
            #pragma unroll
            for (int i = 0; i < 8; i++)
                #pragma unroll
                for (int j = 0; j < 8; j++)
                    acc[i][j] = fmaf(ar[i], br[j], acc[i][j]);
        }
        __syncthreads();
    }
    #pragma unroll
    for (int i = 0; i < 8; i++) {
        long long row = brow + tr + i;
        #pragma unroll
        for (int j = 0; j < 8; j += 4) {
            int col = bcol + tc + j;
            float4 o;
            o.x = acc[i][j + 0] * alpha;
            o.y = acc[i][j + 1] * alpha;
            o.z = acc[i][j + 2] * alpha;
            o.w = acc[i][j + 3] * alpha;
            if (bias) {
                o.x += bias[col + 0]; o.y += bias[col + 1];
                o.z += bias[col + 2]; o.w += bias[col + 3];
            }
            *(float4*)(C + row * N + col) = o;
        }
    }
}

// ---------------- SGEMM C = A·B  (A K-major, B [K,N] N-major) ----------------
__global__ __launch_bounds__(256, 2)
void sgemm_nn(const float* __restrict__ A, const float* __restrict__ B,
              float* __restrict__ C,
              int M, int N, int K,
              long long sA, long long sB, long long sC) {
    A += (long long)blockIdx.z * sA;
    B += (long long)blockIdx.z * sB;
    C += (long long)blockIdx.z * sC;
    __shared__ float As[BK][BM + PAD];
    __shared__ float Bs[BK][BN + PAD];
    int tid = threadIdx.x;
    int brow = blockIdx.y * BM;
    int bcol = blockIdx.x * BN;
    int lr = tid >> 1;
    int lk = (tid & 1) * 4;
    int kr = tid >> 5;             // 0..7
    int nc = (tid & 31) * 4;       // 0..124
    int tr = (tid >> 4) * 8;
    int tc = (tid & 15) * 8;
    float acc[8][8];
    #pragma unroll
    for (int i = 0; i < 8; i++)
        #pragma unroll
        for (int j = 0; j < 8; j++) acc[i][j] = 0.f;

    const float* Ap = A + (long long)(brow + lr) * K + lk;
    const float* Bp = B + (long long)kr * N + bcol + nc;
    for (int k0 = 0; k0 < K; k0 += BK) {
        float4 av = *(const float4*)(Ap + k0);
        float4 bv = *(const float4*)(Bp + (long long)k0 * N);
        As[lk + 0][lr] = av.x; As[lk + 1][lr] = av.y;
        As[lk + 2][lr] = av.z; As[lk + 3][lr] = av.w;
        *(float4*)&Bs[kr][nc] = bv;
        __syncthreads();
        #pragma unroll
        for (int k = 0; k < BK; k++) {
            float4 a0 = *(const float4*)&As[k][tr];
            float4 a1 = *(const float4*)&As[k][tr + 4];
            float4 b0 = *(const float4*)&Bs[k][tc];
            float4 b1 = *(const float4*)&Bs[k][tc + 4];
            float ar[8] = {a0.x, a0.y, a0.z, a0.w, a1.x, a1.y, a1.z, a1.w};
            float br[8] = {b0.x, b0.y, b0.z, b0.w, b1.x, b1.y, b1.z, b1.w};
            #pragma unroll
            for (int i = 0; i < 8; i++)
                #pragma unroll
                for (int j = 0; j < 8; j++)
                    acc[i][j] = fmaf(ar[i], br[j], acc[i][j]);
        }
        __syncthreads();
    }
    #pragma unroll
    for (int i = 0; i < 8; i++) {
        long long row = brow + tr + i;
        #pragma unroll
        for (int j = 0; j < 8; j += 4) {
            int col = bcol + tc + j;
            float4 o = {acc[i][j], acc[i][j + 1], acc[i][j + 2], acc[i][j + 3]};
            *(float4*)(C + row * N + col) = o;
        }
    }
}

// ---------------- softmax over rows of g_s (row length 4096) ----------------
__global__ void softmax_kernel() {
    size_t row = blockIdx.x;
    float4* p = (float4*)(g_s + row * Nn);
    int tid = threadIdx.x;
    float4 v[4];
    float mx = -1e30f;
    #pragma unroll
    for (int i = 0; i < 4; i++) {
        v[i] = p[tid + i * 256];
        mx = fmaxf(mx, fmaxf(fmaxf(v[i].x, v[i].y), fmaxf(v[i].z, v[i].w)));
    }
    __shared__ float sm[256];
    sm[tid] = mx; __syncthreads();
    for (int o = 128; o > 0; o >>= 1) {
        if (tid < o) sm[tid] = fmaxf(sm[tid], sm[tid + o]);
        __syncthreads();
    }
    mx = sm[0];
    __syncthreads();
    float s = 0.f;
    #pragma unroll
    for (int i = 0; i < 4; i++) {
        v[i].x = __expf(v[i].x - mx); v[i].y = __expf(v[i].y - mx);
        v[i].z = __expf(v[i].z - mx); v[i].w = __expf(v[i].w - mx);
        s += v[i].x + v[i].y + v[i].z + v[i].w;
    }
    sm[tid] = s; __syncthreads();
    for (int o = 128; o > 0; o >>= 1) {
        if (tid < o) sm[tid] += sm[tid + o];
        __syncthreads();
    }
    float inv = 1.f / sm[0];
    #pragma unroll
    for (int i = 0; i < 4; i++) {
        v[i].x *= inv; v[i].y *= inv; v[i].z *= inv; v[i].w *= inv;
        p[tid + i * 256] = v[i];
    }
}

// ---------------- residual: out[b,c,n] = x[b,c,n] + y[b,n,c] ----------------
__global__ void residual_kernel(const float* __restrict__ x, float* __restrict__ out) {
    __shared__ float sm[32][33];
    int bz = blockIdx.z;
    int n0 = blockIdx.x * 32;
    int c0 = blockIdx.y * 32;
    int tx = threadIdx.x, ty = threadIdx.y;
    // read y (in g_q) coalesced along c
    sm[ty][tx] = g_q[((size_t)bz * Nn + (n0 + ty)) * Cc + (c0 + tx)];
    __syncthreads();
    size_t idx = ((size_t)bz * Cc + (c0 + ty)) * Nn + (n0 + tx);
    out[idx] = x[idx] + sm[tx][ty];
}

// ---------------- launch ----------------
extern "C" void kernel_launch(void* const* d_in, const int* in_sizes, int n_in,
                              void* d_out, int out_size) {
    const float* x    = (const float*)d_in[0];
    const float* gn_w = (const float*)d_in[1];
    const float* gn_b = (const float*)d_in[2];
    const float* wq   = (const float*)d_in[3];
    const float* bq   = (const float*)d_in[4];
    const float* wk   = (const float*)d_in[5];
    const float* bk   = (const float*)d_in[6];
    const float* wv   = (const float*)d_in[7];
    const float* bv   = (const float*)d_in[8];
    const float* wo   = (const float*)d_in[9];
    const float* bo   = (const float*)d_in[10];
    float* out = (float*)d_out;

    float *h, *q, *k, *v, *s;
    cudaGetSymbolAddress((void**)&h, g_h);
    cudaGetSymbolAddress((void**)&q, g_q);
    cudaGetSymbolAddress((void**)&k, g_k);
    cudaGetSymbolAddress((void**)&v, g_v);
    cudaGetSymbolAddress((void**)&s, g_s);

    const long long NC = (long long)Nn * Cc;           // 2M
    const long long NN = (long long)Nn * Nn;           // 16M
    const int Mtot = Bb * Nn;                          // 32768
    const float scale = 0.044194173824159216f;         // 1/sqrt(512)

    // 1) GN stats
    gn_stats_kernel<<<Bb * GROUPS, 256>>>(x);
    // 2) GN apply + transpose
    gn_apply_kernel<<<dim3(Nn / 32, Cc / 32, Bb), dim3(32, 32)>>>(x, gn_w, gn_b);
    // 3) Q, K, V projections (single big GEMM each: [32768,512] x [512,512]^T)
    dim3 gproj(Cc / BN, Mtot / BM, 1);
    sgemm_tn<<<gproj, 256>>>(h, wq, bq, q, Mtot, Cc, Cc, 1.f, 0, 0, 0);
    sgemm_tn<<<gproj, 256>>>(h, wk, bk, k, Mtot, Cc, Cc, 1.f, 0, 0, 0);
    sgemm_tn<<<gproj, 256>>>(h, wv, bv, v, Mtot, Cc, Cc, 1.f, 0, 0, 0);
    // 4) scores = q k^T * scale  (batched)
    sgemm_tn<<<dim3(Nn / BN, Nn / BM, Bb), 256>>>(q, k, nullptr, s,
                                                  Nn, Nn, Cc, scale, NC, NC, NN);
    // 5) softmax rows
    softmax_kernel<<<Bb * Nn, 256>>>();
    // 6) attn @ V  -> reuse g_h
    sgemm_nn<<<dim3(Cc / BN, Nn / BM, Bb), 256>>>(s, v, h, Nn, Cc, Nn, NN, NC, NC);
    // 7) output projection -> reuse g_q
    sgemm_tn<<<gproj, 256>>>(h, wo, bo, q, Mtot, Cc, Cc, 1.f, 0, 0, 0);
    // 8) residual + transpose back
    residual_kernel<<<dim3(Nn / 32, Cc / 32, Bb), dim3(32, 32)>>>(x, out);
}

// round 3
// speedup vs baseline: 2.3995x; 2.2779x over previous
#include <cuda_runtime.h>
#include <cuda_bf16.h>
#include <math.h>
#include <stdint.h>

#define Cc 512
#define Bb 8
#define Nn 4096
#define GROUPS 8
#define EPS 1e-5f

#define MC ((size_t)Bb * Nn * Cc)       // 16,777,216 elems
#define SC ((size_t)Bb * Nn * Nn)       // 134,217,728 elems
#define NCs ((long long)Nn * Cc)
#define NNs ((long long)Nn * Nn)

// ---------------- scratch ----------------
__device__ __nv_bfloat16 g_hh[MC], g_hl[MC];          // groupnormed tokens (split)
__device__ __nv_bfloat16 g_w4h[4 * Cc * Cc], g_w4l[4 * Cc * Cc]; // wq,wk,wv,wo split
__device__ __nv_bfloat16 g_qh[MC], g_ql[MC];
__device__ __nv_bfloat16 g_kh[MC], g_kl[MC];
__device__ float         g_v[MC];                     // V fp32 (pre-transpose)
__device__ __nv_bfloat16 g_vth[MC], g_vtl[MC];        // V^T split  [b][d][m]
__device__ float         g_s[SC];                     // scores fp32
__device__ __nv_bfloat16 g_ph[SC], g_pl[SC];          // probs split
__device__ __nv_bfloat16 g_aoh[MC], g_aol[MC];        // attn out split
__device__ float         g_y[MC];                     // final proj out
__device__ float         g_stats[Bb * GROUPS * 2];

__device__ __forceinline__ void split_store(float v, __nv_bfloat16* ph, __nv_bfloat16* pl) {
    __nv_bfloat16 h = __float2bfloat16_rn(v);
    *ph = h;
    *pl = __float2bfloat16_rn(v - __bfloat162float(h));
}

// ---------------- 1) group-norm statistics ----------------
__global__ void gn_stats_kernel(const float* __restrict__ x) {
    int bg = blockIdx.x;
    const size_t cnt = (size_t)(Cc / GROUPS) * Nn;
    const float4* p = (const float4*)(x + (size_t)bg * cnt);
    int tid = threadIdx.x;
    float s = 0.f, sq = 0.f;
    for (int i = tid; i < (int)(cnt / 4); i += blockDim.x) {
        float4 v = p[i];
        s  += v.x + v.y + v.z + v.w;
        sq += v.x * v.x + v.y * v.y + v.z * v.z + v.w * v.w;
    }
    __shared__ float ss[256], ssq[256];
    ss[tid] = s; ssq[tid] = sq;
    __syncthreads();
    for (int o = 128; o > 0; o >>= 1) {
        if (tid < o) { ss[tid] += ss[tid + o]; ssq[tid] += ssq[tid + o]; }
        __syncthreads();
    }
    if (tid == 0) {
        float mu  = ss[0] / (float)cnt;
        float var = ssq[0] / (float)cnt - mu * mu;
        g_stats[bg * 2 + 0] = mu;
        g_stats[bg * 2 + 1] = rsqrtf(var + EPS);
    }
}

// ---------------- 2) GN apply + transpose -> split bf16 [B,N,C] ----------------
__global__ void gn_apply_kernel(const float* __restrict__ x,
                                const float* __restrict__ w,
                                const float* __restrict__ b) {
    __shared__ float sm[32][33];
    int bz = blockIdx.z;
    int n0 = blockIdx.x * 32;
    int c0 = blockIdx.y * 32;
    int tx = threadIdx.x, ty = threadIdx.y;
    {
        int c = c0 + ty, n = n0 + tx;
        int g = c >> 6;
        float mu   = g_stats[(bz * GROUPS + g) * 2 + 0];
        float rstd = g_stats[(bz * GROUPS + g) * 2 + 1];
        float v = x[((size_t)bz * Cc + c) * Nn + n];
        sm[ty][tx] = (v - mu) * rstd * w[c] + b[c];
    }
    __syncthreads();
    {
        int n = n0 + ty, c = c0 + tx;
        size_t idx = ((size_t)bz * Nn + n) * Cc + c;
        split_store(sm[tx][ty], g_hh + idx, g_hl + idx);
    }
}

// ---------------- weight split ----------------
__global__ void split_kernel(const float* __restrict__ src,
                             __nv_bfloat16* __restrict__ dh,
                             __nv_bfloat16* __restrict__ dl) {
    int i = blockIdx.x * 256 + threadIdx.x;
    split_store(src[i], dh + i, dl + i);
}

// ---------------- V transpose + split: [b][m][d] f32 -> [b][d][m] bf16x2 ----------------
__global__ void vtrans_kernel() {
    __shared__ float sm[32][33];
    int bz = blockIdx.z;
    int m0 = blockIdx.x * 32;
    int d0 = blockIdx.y * 32;
    int tx = threadIdx.x, ty = threadIdx.y;
    sm[ty][tx] = g_v[((size_t)bz * Nn + (m0 + ty)) * Cc + (d0 + tx)];
    __syncthreads();
    size_t idx = ((size_t)bz * Cc + (d0 + ty)) * Nn + (m0 + tx);
    split_store(sm[tx][ty], g_vth + idx, g_vtl + idx);
}

// ---------------- tensor-core TN GEMM, bf16x3 split ----------------
// C = alpha * A·B^T (+bias).  A[M,K], B[N,K], both hi/lo bf16 planes, K-contiguous.
// Tile 128x128x32. 256 threads, 8 warps (4 M x 2 N), warp tile 32x64.
#define SROW 40               // bf16 row stride in smem (32 + 8 pad)
#define PLANE (128 * SROW)    // elems per plane
#define STAGEE (4 * PLANE)    // elems per stage

__device__ __forceinline__ uint32_t cvta_s(const void* p) {
    return (uint32_t)__cvta_generic_to_shared(p);
}
__device__ __forceinline__ void cp16(uint32_t s, const void* g) {
    asm volatile("cp.async.cg.shared.global [%0], [%1], 16;" :: "r"(s), "l"(g));
}
__device__ __forceinline__ void ldsm4(uint32_t& r0, uint32_t& r1, uint32_t& r2, uint32_t& r3, uint32_t a) {
    asm volatile("ldmatrix.sync.aligned.m8n8.x4.shared.b16 {%0,%1,%2,%3}, [%4];"
                 : "=r"(r0), "=r"(r1), "=r"(r2), "=r"(r3) : "r"(a));
}
__device__ __forceinline__ void mma16816(float* c, const uint32_t* a, const uint32_t* b) {
    asm volatile("mma.sync.aligned.m16n8k16.row.col.f32.bf16.bf16.f32 "
                 "{%0,%1,%2,%3},{%4,%5,%6,%7},{%8,%9},{%0,%1,%2,%3};"
                 : "+f"(c[0]), "+f"(c[1]), "+f"(c[2]), "+f"(c[3])
                 : "r"(a[0]), "r"(a[1]), "r"(a[2]), "r"(a[3]), "r"(b[0]), "r"(b[1]));
}

__global__ __launch_bounds__(256)
void mma_tn(const __nv_bfloat16* __restrict__ Ah, const __nv_bfloat16* __restrict__ Al,
            const __nv_bfloat16* __restrict__ Bh, const __nv_bfloat16* __restrict__ Bl,
            const float* __restrict__ bias,
            float* __restrict__ Cf,
            __nv_bfloat16* __restrict__ Ch, __nv_bfloat16* __restrict__ Cl,
            int M, int N, int K, float alpha,
            long long sA, long long sB, long long sC) {
    extern __shared__ __nv_bfloat16 smbuf[];
    long long zb = blockIdx.z;
    Ah += zb * sA; Al += zb * sA;
    Bh += zb * sB; Bl += zb * sB;
    if (Cf) Cf += zb * sC;
    if (Ch) { Ch += zb * sC; Cl += zb * sC; }

    int tid = threadIdx.x;
    int lane = tid & 31, warp = tid >> 5;
    int wm = warp & 3, wn = warp >> 2;
    int brow = blockIdx.y * 128, bcol = blockIdx.x * 128;
    uint32_t sbase = cvta_s(smbuf);
    int lrow = tid >> 2, lseg = tid & 3;

    float acc[2][8][4];
    #pragma unroll
    for (int i = 0; i < 2; i++)
        #pragma unroll
        for (int j = 0; j < 8; j++)
            #pragma unroll
            for (int q = 0; q < 4; q++) acc[i][j][q] = 0.f;

    auto load_stage = [&](int st, int k0) {
        uint32_t so = sbase + (uint32_t)(st * STAGEE * 2);
        #pragma unroll
        for (int h = 0; h < 2; h++) {
            int r = lrow + h * 64;
            size_t ga = (size_t)(brow + r) * K + k0 + lseg * 8;
            size_t gb = (size_t)(bcol + r) * K + k0 + lseg * 8;
            uint32_t srb = (uint32_t)(r * SROW + lseg * 8) * 2;
            cp16(so + 0 * PLANE * 2 + srb, Ah + ga);
            cp16(so + 1 * PLANE * 2 + srb, Al + ga);
            cp16(so + 2 * PLANE * 2 + srb, Bh + gb);
            cp16(so + 3 * PLANE * 2 + srb, Bl + gb);
        }
    };

    int nk = K >> 5;
    load_stage(0, 0);
    asm volatile("cp.async.commit_group;");

    for (int kt = 0; kt < nk; kt++) {
        if (kt + 1 < nk) {
            load_stage((kt + 1) & 1, (kt + 1) << 5);
            asm volatile("cp.async.commit_group;");
            asm volatile("cp.async.wait_group 1;");
        } else {
            asm volatile("cp.async.wait_group 0;");
        }
        __syncthreads();
        uint32_t so = sbase + (uint32_t)((kt & 1) * STAGEE * 2);
        #pragma unroll
        for (int kk = 0; kk < 2; kk++) {
            // A fragments: phases: row += (lane>>3 & 1)*8, k += (lane>>4)*8
            uint32_t ah[2][4], al[2][4];
            int arow = wm * 32 + ((lane >> 3) & 1) * 8 + (lane & 7);
            int akof = kk * 16 + (lane >> 4) * 8;
            #pragma unroll
            for (int mt = 0; mt < 2; mt++) {
                uint32_t addr = so + (uint32_t)(((arow + mt * 16) * SROW + akof) * 2);
                ldsm4(ah[mt][0], ah[mt][1], ah[mt][2], ah[mt][3], addr);
                ldsm4(al[mt][0], al[mt][1], al[mt][2], al[mt][3], addr + PLANE * 2);
            }
            // B fragments: phases: k += (lane>>3 & 1)*8, row += (lane>>4)*8
            uint32_t bh[8][2], bl[8][2];
            int bphase = lane >> 3;
            int brl = wn * 64 + (lane & 7) + (bphase >> 1) * 8;
            int bkof = kk * 16 + (bphase & 1) * 8;
            #pragma unroll
            for (int np = 0; np < 4; np++) {
                uint32_t addr = so + 2 * PLANE * 2 + (uint32_t)(((brl + np * 16) * SROW + bkof) * 2);
                uint32_t r0, r1, r2, r3;
                ldsm4(r0, r1, r2, r3, addr);
                bh[np * 2][0] = r0; bh[np * 2][1] = r1;
                bh[np * 2 + 1][0] = r2; bh[np * 2 + 1][1] = r3;
                ldsm4(r0, r1, r2, r3, addr + PLANE * 2);
                bl[np * 2][0] = r0; bl[np * 2][1] = r1;
                bl[np * 2 + 1][0] = r2; bl[np * 2 + 1][1] = r3;
            }
            #pragma unroll
            for (int mt = 0; mt < 2; mt++)
                #pragma unroll
                for (int nt = 0; nt < 8; nt++) {
                    mma16816(acc[mt][nt], ah[mt], bh[nt]);
                    mma16816(acc[mt][nt], ah[mt], bl[nt]);
                    mma16816(acc[mt][nt], al[mt], bh[nt]);
                }
        }
        __syncthreads();
    }

    // epilogue
    int gid = lane >> 2, tig = lane & 3;
    #pragma unroll
    for (int nt = 0; nt < 8; nt++) {
        int col = bcol + wn * 64 + nt * 8 + tig * 2;
        float b0 = bias ? bias[col] : 0.f;
        float b1 = bias ? bias[col + 1] : 0.f;
        #pragma unroll
        for (int mt = 0; mt < 2; mt++) {
            int row0 = brow + wm * 32 + mt * 16 + gid;
            float v00 = acc[mt][nt][0] * alpha + b0;
            float v01 = acc[mt][nt][1] * alpha + b1;
            float v10 = acc[mt][nt][2] * alpha + b0;
            float v11 = acc[mt][nt][3] * alpha + b1;
            if (Cf) {
                float2 p0 = {v00, v01}, p1 = {v10, v11};
                *(float2*)(Cf + (size_t)row0 * N + col) = p0;
                *(float2*)(Cf + (size_t)(row0 + 8) * N + col) = p1;
            }
            if (Ch) {
                __nv_bfloat16 h00 = __float2bfloat16_rn(v00);
                __nv_bfloat16 h01 = __float2bfloat16_rn(v01);
                __nv_bfloat16 h10 = __float2bfloat16_rn(v10);
                __nv_bfloat16 h11 = __float2bfloat16_rn(v11);
                __nv_bfloat162 hh0 = {h00, h01}, hh1 = {h10, h11};
                __nv_bfloat162 ll0 = {__float2bfloat16_rn(v00 - __bfloat162float(h00)),
                                      __float2bfloat16_rn(v01 - __bfloat162float(h01))};
                __nv_bfloat162 ll1 = {__float2bfloat16_rn(v10 - __bfloat162float(h10)),
                                      __float2bfloat16_rn(v11 - __bfloat162float(h11))};
                *(__nv_bfloat162*)(Ch + (size_t)row0 * N + col) = hh0;
                *(__nv_bfloat162*)(Cl + (size_t)row0 * N + col) = ll0;
                *(__nv_bfloat162*)(Ch + (size_t)(row0 + 8) * N + col) = hh1;
                *(__nv_bfloat162*)(Cl + (size_t)(row0 + 8) * N + col) = ll1;
            }
        }
    }
}

// ---------------- softmax rows of g_s -> split bf16 probs ----------------
__global__ void softmax_kernel() {
    size_t row = blockIdx.x;
    float4* p = (float4*)(g_s + row * Nn);
    int tid = threadIdx.x;
    float4 v[4];
    float mx = -1e30f;
    #pragma unroll
    for (int i = 0; i < 4; i++) {
        v[i] = p[tid + i * 256];
        mx = fmaxf(mx, fmaxf(fmaxf(v[i].x, v[i].y), fmaxf(v[i].z, v[i].w)));
    }
    __shared__ float sm[256];
    sm[tid] = mx; __syncthreads();
    for (int o = 128; o > 0; o >>= 1) {
        if (tid < o) sm[tid] = fmaxf(sm[tid], sm[tid + o]);
        __syncthreads();
    }
    mx = sm[0];
    __syncthreads();
    float s = 0.f;
    #pragma unroll
    for (int i = 0; i < 4; i++) {
        v[i].x = __expf(v[i].x - mx); v[i].y = __expf(v[i].y - mx);
        v[i].z = __expf(v[i].z - mx); v[i].w = __expf(v[i].w - mx);
        s += v[i].x + v[i].y + v[i].z + v[i].w;
    }
    sm[tid] = s; __syncthreads();
    for (int o = 128; o > 0; o >>= 1) {
        if (tid < o) sm[tid] += sm[tid + o];
        __syncthreads();
    }
    float inv = 1.f / sm[0];
    #pragma unroll
    for (int i = 0; i < 4; i++) {
        float e0 = v[i].x * inv, e1 = v[i].y * inv, e2 = v[i].z * inv, e3 = v[i].w * inv;
        size_t base = row * Nn + (size_t)(tid + i * 256) * 4;
        __nv_bfloat16 h0 = __float2bfloat16_rn(e0), h1 = __float2bfloat16_rn(e1);
        __nv_bfloat16 h2 = __float2bfloat16_rn(e2), h3 = __float2bfloat16_rn(e3);
        __nv_bfloat162 hh0 = {h0, h1}, hh1 = {h2, h3};
        __nv_bfloat162 ll0 = {__float2bfloat16_rn(e0 - __bfloat162float(h0)),
                              __float2bfloat16_rn(e1 - __bfloat162float(h1))};
        __nv_bfloat162 ll1 = {__float2bfloat16_rn(e2 - __bfloat162float(h2)),
                              __float2bfloat16_rn(e3 - __bfloat162float(h3))};
        ((__nv_bfloat162*)(g_ph + base))[0] = hh0;
        ((__nv_bfloat162*)(g_ph + base))[1] = hh1;
        ((__nv_bfloat162*)(g_pl + base))[0] = ll0;
        ((__nv_bfloat162*)(g_pl + base))[1] = ll1;
    }
}

// ---------------- residual: out[b,c,n] = x[b,c,n] + y[b,n,c] ----------------
__global__ void residual_kernel(const float* __restrict__ x, float* __restrict__ out) {
    __shared__ float sm[32][33];
    int bz = blockIdx.z;
    int n0 = blockIdx.x * 32;
    int c0 = blockIdx.y * 32;
    int tx = threadIdx.x, ty = threadIdx.y;
    sm[ty][tx] = g_y[((size_t)bz * Nn + (n0 + ty)) * Cc + (c0 + tx)];
    __syncthreads();
    size_t idx = ((size_t)bz * Cc + (c0 + ty)) * Nn + (n0 + tx);
    out[idx] = x[idx] + sm[tx][ty];
}

// ---------------- launch ----------------
extern "C" void kernel_launch(void* const* d_in, const int* in_sizes, int n_in,
                              void* d_out, int out_size) {
    const float* x    = (const float*)d_in[0];
    const float* gn_w = (const float*)d_in[1];
    const float* gn_b = (const float*)d_in[2];
    const float* wq   = (const float*)d_in[3];
    const float* bq   = (const float*)d_in[4];
    const float* wk   = (const float*)d_in[5];
    const float* bk   = (const float*)d_in[6];
    const float* wv   = (const float*)d_in[7];
    const float* bv   = (const float*)d_in[8];
    const float* wo   = (const float*)d_in[9];
    const float* bo   = (const float*)d_in[10];
    float* out = (float*)d_out;

    __nv_bfloat16 *hh, *hl, *w4h, *w4l, *qh, *ql, *kh, *kl, *vth, *vtl, *ph, *pl, *aoh, *aol;
    float *v, *s, *y;
    cudaGetSymbolAddress((void**)&hh, g_hh);   cudaGetSymbolAddress((void**)&hl, g_hl);
    cudaGetSymbolAddress((void**)&w4h, g_w4h); cudaGetSymbolAddress((void**)&w4l, g_w4l);
    cudaGetSymbolAddress((void**)&qh, g_qh);   cudaGetSymbolAddress((void**)&ql, g_ql);
    cudaGetSymbolAddress((void**)&kh, g_kh);   cudaGetSymbolAddress((void**)&kl, g_kl);
    cudaGetSymbolAddress((void**)&vth, g_vth); cudaGetSymbolAddress((void**)&vtl, g_vtl);
    cudaGetSymbolAddress((void**)&ph, g_ph);   cudaGetSymbolAddress((void**)&pl, g_pl);
    cudaGetSymbolAddress((void**)&aoh, g_aoh); cudaGetSymbolAddress((void**)&aol, g_aol);
    cudaGetSymbolAddress((void**)&v, g_v);
    cudaGetSymbolAddress((void**)&s, g_s);
    cudaGetSymbolAddress((void**)&y, g_y);

    const int Mtot = Bb * Nn;                        // 32768
    const float scale = 0.044194173824159216f;       // 1/sqrt(512)
    const int WSZ = Cc * Cc;                         // 262144
    const int SMEM = STAGEE * 2 * 2;                 // 2 stages * bytes

    cudaFuncSetAttribute(mma_tn, cudaFuncAttributeMaxDynamicSharedMemorySize, SMEM);

    // 1) GN stats + apply (writes split h)
    gn_stats_kernel<<<Bb * GROUPS, 256>>>(x);
    gn_apply_kernel<<<dim3(Nn / 32, Cc / 32, Bb), dim3(32, 32)>>>(x, gn_w, gn_b);
    // 2) split weights
    split_kernel<<<WSZ / 256, 256>>>(wq, w4h + 0 * WSZ, w4l + 0 * WSZ);
    split_kernel<<<WSZ / 256, 256>>>(wk, w4h + 1 * WSZ, w4l + 1 * WSZ);
    split_kernel<<<WSZ / 256, 256>>>(wv, w4h + 2 * WSZ, w4l + 2 * WSZ);
    split_kernel<<<WSZ / 256, 256>>>(wo, w4h + 3 * WSZ, w4l + 3 * WSZ);
    // 3) projections
    dim3 gproj(Cc / 128, Mtot / 128, 1);
    mma_tn<<<gproj, 256, SMEM>>>(hh, hl, w4h + 0 * WSZ, w4l + 0 * WSZ, bq,
                                 nullptr, qh, ql, Mtot, Cc, Cc, 1.f, 0, 0, 0);
    mma_tn<<<gproj, 256, SMEM>>>(hh, hl, w4h + 1 * WSZ, w4l + 1 * WSZ, bk,
                                 nullptr, kh, kl, Mtot, Cc, Cc, 1.f, 0, 0, 0);
    mma_tn<<<gproj, 256, SMEM>>>(hh, hl, w4h + 2 * WSZ, w4l + 2 * WSZ, bv,
                                 v, nullptr, nullptr, Mtot, Cc, Cc, 1.f, 0, 0, 0);
    // 4) V transpose+split
    vtrans_kernel<<<dim3(Nn / 32, Cc / 32, Bb), dim3(32, 32)>>>();
    // 5) scores = q k^T * scale (batched)
    mma_tn<<<dim3(Nn / 128, Nn / 128, Bb), 256, SMEM>>>(qh, ql, kh, kl, nullptr,
                                 s, nullptr, nullptr, Nn, Nn, Cc, scale, NCs, NCs, NNs);
    // 6) softmax -> split probs
    softmax_kernel<<<Bb * Nn, 256>>>();
    // 7) out = P @ V   (TN vs V^T)
    mma_tn<<<dim3(Cc / 128, Nn / 128, Bb), 256, SMEM>>>(ph, pl, vth, vtl, nullptr,
                                 nullptr, aoh, aol, Nn, Cc, Nn, 1.f, NNs, NCs, NCs);
    // 8) final projection
    mma_tn<<<gproj, 256, SMEM>>>(aoh, aol, w4h + 3 * WSZ, w4l + 3 * WSZ, bo,
                                 y, nullptr, nullptr, Mtot, Cc, Cc, 1.f, 0, 0, 0);
    // 9) residual + transpose back
    residual_kernel<<<dim3(Nn / 32, Cc / 32, Bb), dim3(32, 32)>>>(x, out);
}

// round 5
// speedup vs baseline: 2.5483x; 1.0620x over previous
#include <cuda_runtime.h>
#include <cuda_bf16.h>
#include <math.h>
#include <stdint.h>

#define Cc 512
#define Bb 8
#define Nn 4096
#define GROUPS 8
#define EPS 1e-5f

#define MC ((size_t)Bb * Nn * Cc)       // 16,777,216 elems
#define SC ((size_t)Bb * Nn * Nn)       // 134,217,728 elems
#define NCs ((long long)Nn * Cc)
#define NNs ((long long)Nn * Nn)

// ---------------- scratch ----------------
__device__ __nv_bfloat16 g_hh[MC], g_hl[MC];          // groupnormed tokens (split)
__device__ __nv_bfloat16 g_w4h[4 * Cc * Cc], g_w4l[4 * Cc * Cc]; // wq,wk,wv,wo split
__device__ __nv_bfloat16 g_qh[MC], g_ql[MC];
__device__ __nv_bfloat16 g_kh[MC], g_kl[MC];
__device__ float         g_v[MC];                     // V fp32 (pre-transpose)
__device__ __nv_bfloat16 g_vth[MC], g_vtl[MC];        // V^T split  [b][d][m]
__device__ float         g_s[SC];                     // scores fp32
__device__ __nv_bfloat16 g_ph[SC], g_pl[SC];          // probs split
__device__ __nv_bfloat16 g_aoh[MC], g_aol[MC];        // attn out split
__device__ float         g_y[MC];                     // final proj out
__device__ float         g_stats[Bb * GROUPS * 2];

__device__ __forceinline__ void split_store(float v, __nv_bfloat16* ph, __nv_bfloat16* pl) {
    __nv_bfloat16 h = __float2bfloat16_rn(v);
    *ph = h;
    *pl = __float2bfloat16_rn(v - __bfloat162float(h));
}

// ---------------- 1) group-norm statistics ----------------
__global__ void gn_stats_kernel(const float* __restrict__ x) {
    int bg = blockIdx.x;
    const size_t cnt = (size_t)(Cc / GROUPS) * Nn;
    const float4* p = (const float4*)(x + (size_t)bg * cnt);
    int tid = threadIdx.x;
    float s = 0.f, sq = 0.f;
    for (int i = tid; i < (int)(cnt / 4); i += blockDim.x) {
        float4 v = p[i];
        s  += v.x + v.y + v.z + v.w;
        sq += v.x * v.x + v.y * v.y + v.z * v.z + v.w * v.w;
    }
    __shared__ float ss[256], ssq[256];
    ss[tid] = s; ssq[tid] = sq;
    __syncthreads();
    for (int o = 128; o > 0; o >>= 1) {
        if (tid < o) { ss[tid] += ss[tid + o]; ssq[tid] += ssq[tid + o]; }
        __syncthreads();
    }
    if (tid == 0) {
        float mu  = ss[0] / (float)cnt;
        float var = ssq[0] / (float)cnt - mu * mu;
        g_stats[bg * 2 + 0] = mu;
        g_stats[bg * 2 + 1] = rsqrtf(var + EPS);
    }
}

// ---------------- 2) GN apply + transpose -> split bf16 [B,N,C] ----------------
__global__ void gn_apply_kernel(const float* __restrict__ x,
                                const float* __restrict__ w,
                                const float* __restrict__ b) {
    __shared__ float sm[32][33];
    int bz = blockIdx.z;
    int n0 = blockIdx.x * 32;
    int c0 = blockIdx.y * 32;
    int tx = threadIdx.x, ty = threadIdx.y;
    {
        int c = c0 + ty, n = n0 + tx;
        int g = c >> 6;
        float mu   = g_stats[(bz * GROUPS + g) * 2 + 0];
        float rstd = g_stats[(bz * GROUPS + g) * 2 + 1];
        float v = x[((size_t)bz * Cc + c) * Nn + n];
        sm[ty][tx] = (v - mu) * rstd * w[c] + b[c];
    }
    __syncthreads();
    {
        int n = n0 + ty, c = c0 + tx;
        size_t idx = ((size_t)bz * Nn + n) * Cc + c;
        split_store(sm[tx][ty], g_hh + idx, g_hl + idx);
    }
}

// ---------------- weight split ----------------
__global__ void split_kernel(const float* __restrict__ src,
                             __nv_bfloat16* __restrict__ dh,
                             __nv_bfloat16* __restrict__ dl) {
    int i = blockIdx.x * 256 + threadIdx.x;
    split_store(src[i], dh + i, dl + i);
}

// ---------------- V transpose + split: [b][m][d] f32 -> [b][d][m] bf16x2 ----------------
__global__ void vtrans_kernel() {
    __shared__ float sm[32][33];
    int bz = blockIdx.z;
    int m0 = blockIdx.x * 32;
    int d0 = blockIdx.y * 32;
    int tx = threadIdx.x, ty = threadIdx.y;
    sm[ty][tx] = g_v[((size_t)bz * Nn + (m0 + ty)) * Cc + (d0 + tx)];
    __syncthreads();
    size_t idx = ((size_t)bz * Cc + (d0 + ty)) * Nn + (m0 + tx);
    split_store(sm[tx][ty], g_vth + idx, g_vtl + idx);
}

// ---------------- tensor-core TN GEMM, bf16x3 split ----------------
// C = alpha * A·B^T (+bias).  A[M,K], B[N,K], both hi/lo bf16 planes, K-contiguous.
// Tile 128x128x32. 256 threads, 8 warps (4 M x 2 N), warp tile 32x64.
#define SROW 40               // bf16 row stride in smem (32 + 8 pad)
#define PLANE (128 * SROW)    // elems per plane
#define STAGEE (4 * PLANE)    // elems per stage

__device__ __forceinline__ uint32_t cvta_s(const void* p) {
    return (uint32_t)__cvta_generic_to_shared(p);
}
__device__ __forceinline__ void cp16(uint32_t s, const void* g) {
    asm volatile("cp.async.cg.shared.global [%0], [%1], 16;" :: "r"(s), "l"(g));
}
__device__ __forceinline__ void ldsm4(uint32_t& r0, uint32_t& r1, uint32_t& r2, uint32_t& r3, uint32_t a) {
    asm volatile("ldmatrix.sync.aligned.m8n8.x4.shared.b16 {%0,%1,%2,%3}, [%4];"
                 : "=r"(r0), "=r"(r1), "=r"(r2), "=r"(r3) : "r"(a));
}
__device__ __forceinline__ void mma16816(float* c, const uint32_t* a, const uint32_t* b) {
    asm volatile("mma.sync.aligned.m16n8k16.row.col.f32.bf16.bf16.f32 "
                 "{%0,%1,%2,%3},{%4,%5,%6,%7},{%8,%9},{%0,%1,%2,%3};"
                 : "+f"(c[0]), "+f"(c[1]), "+f"(c[2]), "+f"(c[3])
                 : "r"(a[0]), "r"(a[1]), "r"(a[2]), "r"(a[3]), "r"(b[0]), "r"(b[1]));
}

__global__ __launch_bounds__(256, 2)
void mma_tn(const __nv_bfloat16* __restrict__ Ah, const __nv_bfloat16* __restrict__ Al,
            const __nv_bfloat16* __restrict__ Bh, const __nv_bfloat16* __restrict__ Bl,
            const float* __restrict__ bias,
            float* __restrict__ Cf,
            __nv_bfloat16* __restrict__ Ch, __nv_bfloat16* __restrict__ Cl,
            int M, int N, int K, float alpha,
            long long sA, long long sB, long long sC) {
    extern __shared__ __nv_bfloat16 smbuf[];
    long long zb = blockIdx.z;
    Ah += zb * sA; Al += zb * sA;
    Bh += zb * sB; Bl += zb * sB;
    if (Cf) Cf += zb * sC;
    if (Ch) { Ch += zb * sC; Cl += zb * sC; }

    int tid = threadIdx.x;
    int lane = tid & 31, warp = tid >> 5;
    int wm = warp & 3, wn = warp >> 2;
    int brow = blockIdx.y * 128, bcol = blockIdx.x * 128;
    uint32_t sbase = cvta_s(smbuf);
    int lrow = tid >> 1, lseg = tid & 1;

    float acc[2][8][4];
    #pragma unroll
    for (int i = 0; i < 2; i++)
        #pragma unroll
        for (int j = 0; j < 8; j++)
            #pragma unroll
            for (int q = 0; q < 4; q++) acc[i][j][q] = 0.f;

    auto load_stage = [&](int st, int k0) {
        uint32_t so = sbase + (uint32_t)(st * STAGEE * 2);
        size_t ga = (size_t)(brow + lrow) * K + k0 + lseg * 16;
        size_t gb = (size_t)(bcol + lrow) * K + k0 + lseg * 16;
        uint32_t srb = (uint32_t)(lrow * SROW + lseg * 16) * 2;
        cp16(so + 0 * PLANE * 2 + srb, Ah + ga);
        cp16(so + 0 * PLANE * 2 + srb + 16, Ah + ga + 8);
        cp16(so + 1 * PLANE * 2 + srb, Al + ga);
        cp16(so + 1 * PLANE * 2 + srb + 16, Al + ga + 8);
        cp16(so + 2 * PLANE * 2 + srb, Bh + gb);
        cp16(so + 2 * PLANE * 2 + srb + 16, Bh + gb + 8);
        cp16(so + 3 * PLANE * 2 + srb, Bl + gb);
        cp16(so + 3 * PLANE * 2 + srb + 16, Bl + gb + 8);
    };

    int nk = K >> 5;
    load_stage(0, 0);
    asm volatile("cp.async.commit_group;");

    for (int kt = 0; kt < nk; kt++) {
        if (kt + 1 < nk) {
            load_stage((kt + 1) & 1, (kt + 1) << 5);
            asm volatile("cp.async.commit_group;");
            asm volatile("cp.async.wait_group 1;");
        } else {
            asm volatile("cp.async.wait_group 0;");
        }
        __syncthreads();
        uint32_t so = sbase + (uint32_t)((kt & 1) * STAGEE * 2);
        #pragma unroll
        for (int kk = 0; kk < 2; kk++) {
            // A fragments
            uint32_t ah[2][4], al[2][4];
            int arow = wm * 32 + ((lane >> 3) & 1) * 8 + (lane & 7);
            int akof = kk * 16 + (lane >> 4) * 8;
            #pragma unroll
            for (int mt = 0; mt < 2; mt++) {
                uint32_t addr = so + (uint32_t)(((arow + mt * 16) * SROW + akof) * 2);
                ldsm4(ah[mt][0], ah[mt][1], ah[mt][2], ah[mt][3], addr);
                ldsm4(al[mt][0], al[mt][1], al[mt][2], al[mt][3], addr + PLANE * 2);
            }
            // B fragments
            uint32_t bh[8][2], bl[8][2];
            int bphase = lane >> 3;
            int brl = wn * 64 + (lane & 7) + (bphase >> 1) * 8;
            int bkof = kk * 16 + (bphase & 1) * 8;
            #pragma unroll
            for (int np = 0; np < 4; np++) {
                uint32_t addr = so + 2 * PLANE * 2 + (uint32_t)(((brl + np * 16) * SROW + bkof) * 2);
                uint32_t r0, r1, r2, r3;
                ldsm4(r0, r1, r2, r3, addr);
                bh[np * 2][0] = r0; bh[np * 2][1] = r1;
                bh[np * 2 + 1][0] = r2; bh[np * 2 + 1][1] = r3;
                ldsm4(r0, r1, r2, r3, addr + PLANE * 2);
                bl[np * 2][0] = r0; bl[np * 2][1] = r1;
                bl[np * 2 + 1][0] = r2; bl[np * 2 + 1][1] = r3;
            }
            // term-major ordering: max dependency distance per accumulator tile
            #pragma unroll
            for (int mt = 0; mt < 2; mt++)
                #pragma unroll
                for (int nt = 0; nt < 8; nt++)
                    mma16816(acc[mt][nt], ah[mt], bh[nt]);
            #pragma unroll
            for (int mt = 0; mt < 2; mt++)
                #pragma unroll
                for (int nt = 0; nt < 8; nt++)
                    mma16816(acc[mt][nt], ah[mt], bl[nt]);
            #pragma unroll
            for (int mt = 0; mt < 2; mt++)
                #pragma unroll
                for (int nt = 0; nt < 8; nt++)
                    mma16816(acc[mt][nt], al[mt], bh[nt]);
        }
        __syncthreads();
    }

    // epilogue
    int gid = lane >> 2, tig = lane & 3;
    #pragma unroll
    for (int nt = 0; nt < 8; nt++) {
        int col = bcol + wn * 64 + nt * 8 + tig * 2;
        float b0 = bias ? bias[col] : 0.f;
        float b1 = bias ? bias[col + 1] : 0.f;
        #pragma unroll
        for (int mt = 0; mt < 2; mt++) {
            int row0 = brow + wm * 32 + mt * 16 + gid;
            float v00 = acc[mt][nt][0] * alpha + b0;
            float v01 = acc[mt][nt][1] * alpha + b1;
            float v10 = acc[mt][nt][2] * alpha + b0;
            float v11 = acc[mt][nt][3] * alpha + b1;
            if (Cf) {
                float2 p0 = {v00, v01}, p1 = {v10, v11};
                *(float2*)(Cf + (size_t)row0 * N + col) = p0;
                *(float2*)(Cf + (size_t)(row0 + 8) * N + col) = p1;
            }
            if (Ch) {
                __nv_bfloat16 h00 = __float2bfloat16_rn(v00);
                __nv_bfloat16 h01 = __float2bfloat16_rn(v01);
                __nv_bfloat16 h10 = __float2bfloat16_rn(v10);
                __nv_bfloat16 h11 = __float2bfloat16_rn(v11);
                __nv_bfloat162 hh0 = {h00, h01}, hh1 = {h10, h11};
                __nv_bfloat162 ll0 = {__float2bfloat16_rn(v00 - __bfloat162float(h00)),
                                      __float2bfloat16_rn(v01 - __bfloat162float(h01))};
                __nv_bfloat162 ll1 = {__float2bfloat16_rn(v10 - __bfloat162float(h10)),
                                      __float2bfloat16_rn(v11 - __bfloat162float(h11))};
                *(__nv_bfloat162*)(Ch + (size_t)row0 * N + col) = hh0;
                *(__nv_bfloat162*)(Cl + (size_t)row0 * N + col) = ll0;
                *(__nv_bfloat162*)(Ch + (size_t)(row0 + 8) * N + col) = hh1;
                *(__nv_bfloat162*)(Cl + (size_t)(row0 + 8) * N + col) = ll1;
            }
        }
    }
}

// ---------------- softmax rows of g_s -> split bf16 probs ----------------
__global__ void softmax_kernel() {
    size_t row = blockIdx.x;
    float4* p = (float4*)(g_s + row * Nn);
    int tid = threadIdx.x;
    float4 v[4];
    float mx = -1e30f;
    #pragma unroll
    for (int i = 0; i < 4; i++) {
        v[i] = p[tid + i * 256];
        mx = fmaxf(mx, fmaxf(fmaxf(v[i].x, v[i].y), fmaxf(v[i].z, v[i].w)));
    }
    __shared__ float sm[256];
    sm[tid] = mx; __syncthreads();
    for (int o = 128; o > 0; o >>= 1) {
        if (tid < o) sm[tid] = fmaxf(sm[tid], sm[tid + o]);
        __syncthreads();
    }
    mx = sm[0];
    __syncthreads();
    float s = 0.f;
    #pragma unroll
    for (int i = 0; i < 4; i++) {
        v[i].x = __expf(v[i].x - mx); v[i].y = __expf(v[i].y - mx);
        v[i].z = __expf(v[i].z - mx); v[i].w = __expf(v[i].w - mx);
        s += v[i].x + v[i].y + v[i].z + v[i].w;
    }
    sm[tid] = s; __syncthreads();
    for (int o = 128; o > 0; o >>= 1) {
        if (tid < o) sm[tid] += sm[tid + o];
        __syncthreads();
    }
    float inv = 1.f / sm[0];
    #pragma unroll
    for (int i = 0; i < 4; i++) {
        float e0 = v[i].x * inv, e1 = v[i].y * inv, e2 = v[i].z * inv, e3 = v[i].w * inv;
        size_t base = row * Nn + (size_t)(tid + i * 256) * 4;
        __nv_bfloat16 h0 = __float2bfloat16_rn(e0), h1 = __float2bfloat16_rn(e1);
        __nv_bfloat16 h2 = __float2bfloat16_rn(e2), h3 = __float2bfloat16_rn(e3);
        __nv_bfloat162 hh0 = {h0, h1}, hh1 = {h2, h3};
        __nv_bfloat162 ll0 = {__float2bfloat16_rn(e0 - __bfloat162float(h0)),
                              __float2bfloat16_rn(e1 - __bfloat162float(h1))};
        __nv_bfloat162 ll1 = {__float2bfloat16_rn(e2 - __bfloat162float(h2)),
                              __float2bfloat16_rn(e3 - __bfloat162float(h3))};
        ((__nv_bfloat162*)(g_ph + base))[0] = hh0;
        ((__nv_bfloat162*)(g_ph + base))[1] = hh1;
        ((__nv_bfloat162*)(g_pl + base))[0] = ll0;
        ((__nv_bfloat162*)(g_pl + base))[1] = ll1;
    }
}

// ---------------- residual: out[b,c,n] = x[b,c,n] + y[b,n,c] ----------------
__global__ void residual_kernel(const float* __restrict__ x, float* __restrict__ out) {
    __shared__ float sm[32][33];
    int bz = blockIdx.z;
    int n0 = blockIdx.x * 32;
    int c0 = blockIdx.y * 32;
    int tx = threadIdx.x, ty = threadIdx.y;
    sm[ty][tx] = g_y[((size_t)bz * Nn + (n0 + ty)) * Cc + (c0 + tx)];
    __syncthreads();
    size_t idx = ((size_t)bz * Cc + (c0 + ty)) * Nn + (n0 + tx);
    out[idx] = x[idx] + sm[tx][ty];
}

// ---------------- launch ----------------
extern "C" void kernel_launch(void* const* d_in, const int* in_sizes, int n_in,
                              void* d_out, int out_size) {
    const float* x    = (const float*)d_in[0];
    const float* gn_w = (const float*)d_in[1];
    const float* gn_b = (const float*)d_in[2];
    const float* wq   = (const float*)d_in[3];
    const float* bq   = (const float*)d_in[4];
    const float* wk   = (const float*)d_in[5];
    const float* bk   = (const float*)d_in[6];
    const float* wv   = (const float*)d_in[7];
    const float* bv   = (const float*)d_in[8];
    const float* wo   = (const float*)d_in[9];
    const float* bo   = (const float*)d_in[10];
    float* out = (float*)d_out;

    __nv_bfloat16 *hh, *hl, *w4h, *w4l, *qh, *ql, *kh, *kl, *vth, *vtl, *ph, *pl, *aoh, *aol;
    float *v, *s, *y;
    cudaGetSymbolAddress((void**)&hh, g_hh);   cudaGetSymbolAddress((void**)&hl, g_hl);
    cudaGetSymbolAddress((void**)&w4h, g_w4h); cudaGetSymbolAddress((void**)&w4l, g_w4l);
    cudaGetSymbolAddress((void**)&qh, g_qh);   cudaGetSymbolAddress((void**)&ql, g_ql);
    cudaGetSymbolAddress((void**)&kh, g_kh);   cudaGetSymbolAddress((void**)&kl, g_kl);
    cudaGetSymbolAddress((void**)&vth, g_vth); cudaGetSymbolAddress((void**)&vtl, g_vtl);
    cudaGetSymbolAddress((void**)&ph, g_ph);   cudaGetSymbolAddress((void**)&pl, g_pl);
    cudaGetSymbolAddress((void**)&aoh, g_aoh); cudaGetSymbolAddress((void**)&aol, g_aol);
    cudaGetSymbolAddress((void**)&v, g_v);
    cudaGetSymbolAddress((void**)&s, g_s);
    cudaGetSymbolAddress((void**)&y, g_y);

    const int Mtot = Bb * Nn;                        // 32768
    const float scale = 0.044194173824159216f;       // 1/sqrt(512)
    const int WSZ = Cc * Cc;                         // 262144
    const int SMEM = STAGEE * 2 * 2;                 // 2 stages * bytes

    cudaFuncSetAttribute(mma_tn, cudaFuncAttributeMaxDynamicSharedMemorySize, SMEM);

    // 1) GN stats + apply (writes split h)
    gn_stats_kernel<<<Bb * GROUPS, 256>>>(x);
    gn_apply_kernel<<<dim3(Nn / 32, Cc / 32, Bb), dim3(32, 32)>>>(x, gn_w, gn_b);
    // 2) split weights
    split_kernel<<<WSZ / 256, 256>>>(wq, w4h + 0 * WSZ, w4l + 0 * WSZ);
    split_kernel<<<WSZ / 256, 256>>>(wk, w4h + 1 * WSZ, w4l + 1 * WSZ);
    split_kernel<<<WSZ / 256, 256>>>(wv, w4h + 2 * WSZ, w4l + 2 * WSZ);
    split_kernel<<<WSZ / 256, 256>>>(wo, w4h + 3 * WSZ, w4l + 3 * WSZ);
    // 3) projections
    dim3 gproj(Cc / 128, Mtot / 128, 1);
    mma_tn<<<gproj, 256, SMEM>>>(hh, hl, w4h + 0 * WSZ, w4l + 0 * WSZ, bq,
                                 nullptr, qh, ql, Mtot, Cc, Cc, 1.f, 0, 0, 0);
    mma_tn<<<gproj, 256, SMEM>>>(hh, hl, w4h + 1 * WSZ, w4l + 1 * WSZ, bk,
                                 nullptr, kh, kl, Mtot, Cc, Cc, 1.f, 0, 0, 0);
    mma_tn<<<gproj, 256, SMEM>>>(hh, hl, w4h + 2 * WSZ, w4l + 2 * WSZ, bv,
                                 v, nullptr, nullptr, Mtot, Cc, Cc, 1.f, 0, 0, 0);
    // 4) V transpose+split
    vtrans_kernel<<<dim3(Nn / 32, Cc / 32, Bb), dim3(32, 32)>>>();
    // 5) scores = q k^T * scale (batched)
    mma_tn<<<dim3(Nn / 128, Nn / 128, Bb), 256, SMEM>>>(qh, ql, kh, kl, nullptr,
                                 s, nullptr, nullptr, Nn, Nn, Cc, scale, NCs, NCs, NNs);
    // 6) softmax -> split probs
    softmax_kernel<<<Bb * Nn, 256>>>();
    // 7) out = P @ V   (TN vs V^T)
    mma_tn<<<dim3(Cc / 128, Nn / 128, Bb), 256, SMEM>>>(ph, pl, vth, vtl, nullptr,
                                 nullptr, aoh, aol, Nn, Cc, Nn, 1.f, NNs, NCs, NCs);
    // 8) final projection
    mma_tn<<<gproj, 256, SMEM>>>(aoh, aol, w4h + 3 * WSZ, w4l + 3 * WSZ, bo,
                                 y, nullptr, nullptr, Mtot, Cc, Cc, 1.f, 0, 0, 0);
    // 9) residual + transpose back
    residual_kernel<<<dim3(Nn / 32, Cc / 32, Bb), dim3(32, 32)>>>(x, out);
}